// round 1
// baseline (speedup 1.0000x reference)
#include <cuda_runtime.h>
#include <cstdint>

#define Bn   16
#define Cn   256
#define Tn   1024
#define KEYn 256
#define INV_SQRT_K 0.0625f

// ---------------- scratch (device globals; no allocation allowed) ----------
__device__ float g_q[Bn * Tn * KEYn];
__device__ float g_k[Bn * Tn * KEYn];
__device__ float g_v[Bn * Tn * Cn];
__device__ float g_attn[(size_t)Bn * Tn * Tn];   // scores -> attn weights (in place)
__device__ float g_rowsum[Bn * Tn];
__device__ float g_wx[Bn * Tn];
__device__ float g_oa[Bn * Cn * Tn];             // attention output, [B,C,T]
__device__ float g_h1[Bn * Cn * Tn];             // conv1 output
__device__ float g_w1[Cn * Cn * 3];              // weight-normed conv weights
__device__ float g_w2[Cn * Cn * 3];

__device__ __forceinline__ float neg_inf() { return __int_as_float(0xff800000u); }

// ---------------- weight norm: w = g * v / ||v||_(in,k) --------------------
__global__ __launch_bounds__(256) void wnorm_kernel(const float* __restrict__ v,
                                                    const float* __restrict__ g,
                                                    int which) {
    float* w = which ? g_w2 : g_w1;
    int o = blockIdx.x;
    int tid = threadIdx.x;
    __shared__ float red[256];
    float s = 0.f;
    for (int i = tid; i < Cn * 3; i += 256) {
        float t = v[o * Cn * 3 + i];
        s += t * t;
    }
    red[tid] = s;
    __syncthreads();
    for (int st = 128; st > 0; st >>= 1) {
        if (tid < st) red[tid] += red[tid + st];
        __syncthreads();
    }
    float scale = g[o] * rsqrtf(red[0]);
    for (int i = tid; i < Cn * 3; i += 256)
        w[o * Cn * 3 + i] = v[o * Cn * 3 + i] * scale;
}

// ---------------- q/k/v GEMM: out[b,t,n] = sum_c x[b,c,t] * W[c,n] + bias --
// which: 0 -> g_q, 1 -> g_k, 2 -> g_v
__global__ __launch_bounds__(256) void gemm_qkv(const float* __restrict__ x,
                                                const float* __restrict__ W,
                                                const float* __restrict__ bias,
                                                int which) {
    float* out = (which == 0) ? g_q : (which == 1) ? g_k : g_v;
    const int N = 256;
    __shared__ float As[16][64];   // [c_k][t]
    __shared__ float Bs[16][64];   // [c_k][n]
    int b = blockIdx.z;
    int t0 = blockIdx.x * 64, n0 = blockIdx.y * 64;
    int tid = threadIdx.x;
    int tx = tid & 15, ty = tid >> 4;
    int lk = tid >> 4, lm = (tid & 15) * 4;
    const float* xb = x + (size_t)b * Cn * Tn;
    float acc[4][4] = {};
    for (int c0 = 0; c0 < Cn; c0 += 16) {
        *(float4*)&As[lk][lm] = *(const float4*)&xb[(c0 + lk) * Tn + t0 + lm];
        *(float4*)&Bs[lk][lm] = *(const float4*)&W[(c0 + lk) * N + n0 + lm];
        __syncthreads();
#pragma unroll
        for (int kk = 0; kk < 16; kk++) {
            float4 a4 = *(float4*)&As[kk][ty * 4];
            float4 b4 = *(float4*)&Bs[kk][tx * 4];
            float av[4] = {a4.x, a4.y, a4.z, a4.w};
            float bv[4] = {b4.x, b4.y, b4.z, b4.w};
#pragma unroll
            for (int i = 0; i < 4; i++)
#pragma unroll
                for (int j = 0; j < 4; j++) acc[i][j] += av[i] * bv[j];
        }
        __syncthreads();
    }
    float4 bb = *(const float4*)&bias[n0 + tx * 4];
    float bvv[4] = {bb.x, bb.y, bb.z, bb.w};
#pragma unroll
    for (int i = 0; i < 4; i++) {
        int t = t0 + ty * 4 + i;
        float4 o;
        o.x = acc[i][0] + bvv[0];
        o.y = acc[i][1] + bvv[1];
        o.z = acc[i][2] + bvv[2];
        o.w = acc[i][3] + bvv[3];
        *(float4*)&out[((size_t)b * Tn + t) * N + n0 + tx * 4] = o;
    }
}

// ------------- scores: S[b,j,i] = (i<=j) ? q[b,j]·k[b,i] / 16 : -inf -------
__global__ __launch_bounds__(256) void gemm_scores() {
    int b = blockIdx.z;
    int i0 = blockIdx.x * 64, j0 = blockIdx.y * 64;
    int tid = threadIdx.x;
    int tx = tid & 15, ty = tid >> 4;
    float* S = g_attn + (size_t)b * Tn * Tn;
    if (i0 > j0) {  // tile fully masked (i > j everywhere)
        float ni = neg_inf();
        float4 o = make_float4(ni, ni, ni, ni);
#pragma unroll
        for (int i = 0; i < 4; i++) {
            int j = j0 + ty * 4 + i;
            *(float4*)&S[(size_t)j * Tn + i0 + tx * 4] = o;
        }
        return;
    }
    __shared__ float Qs[16][68];   // [k][j]  (transposed on load, 68 keeps 16B align)
    __shared__ float Ks[16][68];   // [k][i]
    int lj = tid >> 2, ls = (tid & 3) * 4;
    const float* qb = g_q + (size_t)b * Tn * KEYn;
    const float* kb = g_k + (size_t)b * Tn * KEYn;
    float acc[4][4] = {};
    for (int kc = 0; kc < KEYn; kc += 16) {
        float4 qv = *(const float4*)&qb[(size_t)(j0 + lj) * KEYn + kc + ls];
        Qs[ls + 0][lj] = qv.x; Qs[ls + 1][lj] = qv.y;
        Qs[ls + 2][lj] = qv.z; Qs[ls + 3][lj] = qv.w;
        float4 kv = *(const float4*)&kb[(size_t)(i0 + lj) * KEYn + kc + ls];
        Ks[ls + 0][lj] = kv.x; Ks[ls + 1][lj] = kv.y;
        Ks[ls + 2][lj] = kv.z; Ks[ls + 3][lj] = kv.w;
        __syncthreads();
#pragma unroll
        for (int kk = 0; kk < 16; kk++) {
            float4 a4 = *(float4*)&Qs[kk][ty * 4];
            float4 b4 = *(float4*)&Ks[kk][tx * 4];
            float av[4] = {a4.x, a4.y, a4.z, a4.w};
            float bv[4] = {b4.x, b4.y, b4.z, b4.w};
#pragma unroll
            for (int i = 0; i < 4; i++)
#pragma unroll
                for (int j = 0; j < 4; j++) acc[i][j] += av[i] * bv[j];
        }
        __syncthreads();
    }
    float ni = neg_inf();
#pragma unroll
    for (int i = 0; i < 4; i++) {
        int j = j0 + ty * 4 + i;
        int ib = i0 + tx * 4;
        float4 o;
        o.x = (ib + 0 <= j) ? acc[i][0] * INV_SQRT_K : ni;
        o.y = (ib + 1 <= j) ? acc[i][1] * INV_SQRT_K : ni;
        o.z = (ib + 2 <= j) ? acc[i][2] * INV_SQRT_K : ni;
        o.w = (ib + 3 <= j) ? acc[i][3] * INV_SQRT_K : ni;
        *(float4*)&S[(size_t)j * Tn + ib] = o;
    }
}

// ------------- softmax over j (query axis) for each column i ---------------
// block: 64 columns x 4 j-slices, coalesced strided column reads.
__global__ __launch_bounds__(256) void col_softmax() {
    int b = blockIdx.y;
    int col = threadIdx.x & 63;
    int icol = blockIdx.x * 64 + col;
    int slice = threadIdx.x >> 6;  // 0..3
    float* base = g_attn + (size_t)b * Tn * Tn + icol;
    float ni = neg_inf();
    int j0 = slice * 256;
    float m = ni, s = 0.f;
    for (int j = j0; j < j0 + 256; j++) {
        float v = base[(size_t)j * Tn];
        if (v > ni) {
            float nm = fmaxf(m, v);
            s = s * __expf(m - nm) + __expf(v - nm);
            m = nm;
        }
    }
    __shared__ float sm[4][64], ss[4][64];
    __shared__ float fm[64], fs[64];
    sm[slice][col] = m;
    ss[slice][col] = s;
    __syncthreads();
    if (threadIdx.x < 64) {
        int c = threadIdx.x;
        float M = ni;
#pragma unroll
        for (int k = 0; k < 4; k++) M = fmaxf(M, sm[k][c]);
        float Ssum = 0.f;
#pragma unroll
        for (int k = 0; k < 4; k++) {
            float mm = sm[k][c];
            if (mm > ni) Ssum += ss[k][c] * __expf(mm - M);
        }
        fm[c] = M;
        fs[c] = 1.f / Ssum;
    }
    __syncthreads();
    float M = fm[col], inv = fs[col];
    for (int j = j0; j < j0 + 256; j++) {
        float v = base[(size_t)j * Tn];
        base[(size_t)j * Tn] = (v > ni) ? __expf(v - M) * inv : 0.f;
    }
}

// ------------- rowsum[b,j] = sum_i attn[b,j,i] -----------------------------
__global__ __launch_bounds__(256) void row_sum() {
    int b = blockIdx.y;
    int j = blockIdx.x * 8 + (threadIdx.x >> 5);
    int lane = threadIdx.x & 31;
    const float* row = g_attn + (size_t)b * Tn * Tn + (size_t)j * Tn;
    float s = 0.f;
    for (int i = lane; i < Tn; i += 32) s += row[i];
#pragma unroll
    for (int o = 16; o > 0; o >>= 1) s += __shfl_xor_sync(0xffffffffu, s, o);
    if (lane == 0) g_rowsum[b * Tn + j] = s;
}

// ------------- weight_x[b,:] = softmax_j(rowsum[b,:]) ----------------------
__global__ __launch_bounds__(256) void wx_softmax() {
    int b = blockIdx.x;
    int tid = threadIdx.x;
    __shared__ float red[256];
    const float* r = g_rowsum + b * Tn;
    float m = -1e30f;
    for (int j = tid; j < Tn; j += 256) m = fmaxf(m, r[j]);
    red[tid] = m;
    __syncthreads();
    for (int st = 128; st > 0; st >>= 1) {
        if (tid < st) red[tid] = fmaxf(red[tid], red[tid + st]);
        __syncthreads();
    }
    m = red[0];
    __syncthreads();
    float sum = 0.f;
    for (int j = tid; j < Tn; j += 256) sum += __expf(r[j] - m);
    red[tid] = sum;
    __syncthreads();
    for (int st = 128; st > 0; st >>= 1) {
        if (tid < st) red[tid] += red[tid + st];
        __syncthreads();
    }
    float inv = 1.f / red[0];
    for (int j = tid; j < Tn; j += 256)
        g_wx[b * Tn + j] = __expf(r[j] - m) * inv;
}

// ------------- out_attn[b,c,j] = sum_i attn[b,j,i] * v[b,i,c] --------------
__global__ __launch_bounds__(256) void gemm_av() {
    int b = blockIdx.z;
    int j0 = blockIdx.x * 64, c0 = blockIdx.y * 64;
    int tid = threadIdx.x;
    int tx = tid & 15, ty = tid >> 4;
    __shared__ float As[16][68];   // [i_k][j] transposed from attn
    __shared__ float Bs[16][64];   // [i_k][c] direct from v
    const float* A = g_attn + (size_t)b * Tn * Tn;
    const float* V = g_v + (size_t)b * Tn * Cn;
    int lj = tid >> 2, ls = (tid & 3) * 4;
    int lk = tid >> 4, lm = (tid & 15) * 4;
    float acc[4][4] = {};
    int kend = j0 + 64;   // causal: attn[j,i]==0 for i>j
    for (int i0 = 0; i0 < kend; i0 += 16) {
        float4 av = *(const float4*)&A[(size_t)(j0 + lj) * Tn + i0 + ls];
        As[ls + 0][lj] = av.x; As[ls + 1][lj] = av.y;
        As[ls + 2][lj] = av.z; As[ls + 3][lj] = av.w;
        *(float4*)&Bs[lk][lm] = *(const float4*)&V[(size_t)(i0 + lk) * Cn + c0 + lm];
        __syncthreads();
#pragma unroll
        for (int kk = 0; kk < 16; kk++) {
            float4 a4 = *(float4*)&As[kk][ty * 4];
            float4 b4 = *(float4*)&Bs[kk][tx * 4];
            float avv[4] = {a4.x, a4.y, a4.z, a4.w};
            float bvv[4] = {b4.x, b4.y, b4.z, b4.w};
#pragma unroll
            for (int i = 0; i < 4; i++)
#pragma unroll
                for (int j = 0; j < 4; j++) acc[i][j] += avv[i] * bvv[j];
        }
        __syncthreads();
    }
#pragma unroll
    for (int i = 0; i < 4; i++)
#pragma unroll
        for (int jn = 0; jn < 4; jn++)
            g_oa[((size_t)b * Cn + c0 + tx * 4 + jn) * Tn + j0 + ty * 4 + i] = acc[i][jn];
}

// ------------- causal conv (KS=3, pad-left 2) + relu; WHICH=2 fuses final --
// WHICH==1: in=g_oa, w=g_w1, out=g_h1 ;  WHICH==2: in=g_h1, w=g_w2, out=param
template <int WHICH>
__global__ __launch_bounds__(256) void conv_kernel(const float* __restrict__ bias,
                                                   const float* __restrict__ x,
                                                   float* __restrict__ out_final) {
    const float* in = (WHICH == 1) ? g_oa : g_h1;
    const float* w  = (WHICH == 1) ? g_w1 : g_w2;
    float* out = (WHICH == 1) ? g_h1 : out_final;
    int b = blockIdx.z;
    int t0 = blockIdx.x * 64, o0 = blockIdx.y * 64;
    int tid = threadIdx.x;
    int tx = tid & 15, ty = tid >> 4;
    __shared__ float Ws[64][48];   // [o][c*3+k] (row stride 192B, 16B aligned)
    __shared__ float In_s[16][72]; // [c][t0-2 .. t0+63] window (66 used)
    float acc[4][4] = {};
    int wrow = tid >> 2;
    for (int c0 = 0; c0 < Cn; c0 += 16) {
#pragma unroll
        for (int r = 0; r < 3; r++) {
            int off = ((tid & 3) + 4 * r) * 4;
            *(float4*)&Ws[wrow][off] =
                *(const float4*)&w[(o0 + wrow) * (Cn * 3) + c0 * 3 + off];
        }
        for (int idx = tid; idx < 16 * 66; idx += 256) {
            int cc = idx / 66, tt = idx % 66;
            int gt = t0 - 2 + tt;
            In_s[cc][tt] = (gt >= 0)
                ? in[((size_t)b * Cn + c0 + cc) * Tn + gt] : 0.f;
        }
        __syncthreads();
#pragma unroll
        for (int cc = 0; cc < 16; cc++) {
            float win[6];
#pragma unroll
            for (int u = 0; u < 6; u++) win[u] = In_s[cc][tx * 4 + u];
#pragma unroll
            for (int i = 0; i < 4; i++) {
                float w0 = Ws[ty * 4 + i][cc * 3 + 0];
                float w1 = Ws[ty * 4 + i][cc * 3 + 1];
                float w2 = Ws[ty * 4 + i][cc * 3 + 2];
#pragma unroll
                for (int j = 0; j < 4; j++)
                    acc[i][j] += w0 * win[j] + w1 * win[j + 1] + w2 * win[j + 2];
            }
        }
        __syncthreads();
    }
    float wxv[4];
    if (WHICH == 2) {
#pragma unroll
        for (int j = 0; j < 4; j++) wxv[j] = g_wx[b * Tn + t0 + tx * 4 + j];
    }
#pragma unroll
    for (int i = 0; i < 4; i++) {
        int o = o0 + ty * 4 + i;
        float bo = bias[o];
        float vals[4];
#pragma unroll
        for (int j = 0; j < 4; j++) {
            float h = fmaxf(acc[i][j] + bo, 0.f);
            if (WHICH == 2) {
                int t = t0 + tx * 4 + j;
                float xv = x[((size_t)b * Cn + o) * Tn + t];
                h = fmaxf(h + xv + wxv[j] * xv, 0.f);
            }
            vals[j] = h;
        }
        *(float4*)&out[((size_t)b * Cn + o) * Tn + t0 + tx * 4] =
            make_float4(vals[0], vals[1], vals[2], vals[3]);
    }
}

// ---------------------------------------------------------------------------
extern "C" void kernel_launch(void* const* d_in, const int* in_sizes, int n_in,
                              void* d_out, int out_size) {
    const float* x   = (const float*)d_in[0];
    const float* Wq  = (const float*)d_in[1];
    const float* bq  = (const float*)d_in[2];
    const float* Wk  = (const float*)d_in[3];
    const float* bk  = (const float*)d_in[4];
    const float* Wv  = (const float*)d_in[5];
    const float* bv  = (const float*)d_in[6];
    const float* c1v = (const float*)d_in[7];
    const float* c1g = (const float*)d_in[8];
    const float* c1b = (const float*)d_in[9];
    const float* c2v = (const float*)d_in[10];
    const float* c2g = (const float*)d_in[11];
    const float* c2b = (const float*)d_in[12];
    float* out = (float*)d_out;

    wnorm_kernel<<<Cn, 256>>>(c1v, c1g, 0);
    wnorm_kernel<<<Cn, 256>>>(c2v, c2g, 1);

    dim3 gQ(Tn / 64, 256 / 64, Bn);
    gemm_qkv<<<gQ, 256>>>(x, Wq, bq, 0);
    gemm_qkv<<<gQ, 256>>>(x, Wk, bk, 1);
    gemm_qkv<<<gQ, 256>>>(x, Wv, bv, 2);

    gemm_scores<<<dim3(Tn / 64, Tn / 64, Bn), 256>>>();
    col_softmax<<<dim3(Tn / 64, Bn), 256>>>();
    row_sum<<<dim3(Tn / 8, Bn), 256>>>();
    wx_softmax<<<Bn, 256>>>();
    gemm_av<<<dim3(Tn / 64, Cn / 64, Bn), 256>>>();

    conv_kernel<1><<<dim3(Tn / 64, Cn / 64, Bn), 256>>>(c1b, x, nullptr);
    conv_kernel<2><<<dim3(Tn / 64, Cn / 64, Bn), 256>>>(c2b, x, out);
}